// round 6
// baseline (speedup 1.0000x reference)
#include <cuda_runtime.h>
#include <cstdint>
#include <math.h>

#define BB   8
#define CC   256
#define KCC  32
#define NN   16384
#define TPX  128          // pass1 tile pixels
#define T1   4            // tiles per CTA
#define NB1  32           // CTAs per batch (32*4*128 = 16384)

#define LDW  260          // Ws row stride (floats): 260%32==4 -> A frags conflict-free
#define LDX  136          // xs row stride: 136%32==8 -> stage-B B frags conflict-free
#define LDK  132          // km row stride: 132%32==4 -> stage-C A frags conflict-free

// smem float offsets (pass1)
#define F_BIAS 0
#define F_WS   64
#define F_XS   (F_WS + 64 * LDW)          // 16704
#define F_KM   (F_XS + 256 * LDX)         // 51520
#define SMEM1_FLOATS (F_KM + 32 * LDK)    // 55744
#define SMEM1_BYTES  (SMEM1_FLOATS * 4)   // 222976

// pass2 smem
#define P2_LDA 36         // kvT row stride: 36%32==4 -> A frags conflict-free
#define P2_LDB 132        // qm row stride: 132%32==4 -> B frags conflict-free

// Scratch (device globals)
__device__ __align__(16) float g_qm[(size_t)BB * KCC * NN]; // 16 MB fp32 [b][kc][n]
__device__ __align__(16) float g_S [BB * KCC * CC];
__device__ __align__(16) float g_z [BB * KCC];
__device__ __align__(16) float g_kv[BB * KCC * CC];
__device__ __align__(16) float g_zf[BB * KCC];

extern __shared__ float smf[];

__device__ __forceinline__ void cp_async16(uint32_t smem_dst, const void* gmem_src) {
    asm volatile("cp.async.cg.shared.global [%0], [%1], 16;\n" :: "r"(smem_dst), "l"(gmem_src));
}
__device__ __forceinline__ void cp_commit() {
    asm volatile("cp.async.commit_group;\n");
}
__device__ __forceinline__ void cp_wait_n(int n) {
    switch (n) {
        case 0: asm volatile("cp.async.wait_group 0;\n"); break;
        case 1: asm volatile("cp.async.wait_group 1;\n"); break;
        case 2: asm volatile("cp.async.wait_group 2;\n"); break;
        default: asm volatile("cp.async.wait_group 3;\n"); break;
    }
}
__device__ __forceinline__ uint32_t smem_u32(const void* p) {
    uint32_t a;
    asm("{ .reg .u64 t; cvta.to.shared.u64 t, %1; cvt.u32.u64 %0, t; }" : "=r"(a) : "l"(p));
    return a;
}
__device__ __forceinline__ void mma_tf32(float d[4], const uint32_t a[4], const uint32_t b[2]) {
    asm volatile(
        "mma.sync.aligned.m16n8k8.row.col.f32.tf32.tf32.f32 "
        "{%0,%1,%2,%3}, {%4,%5,%6,%7}, {%8,%9}, {%0,%1,%2,%3};\n"
        : "+f"(d[0]), "+f"(d[1]), "+f"(d[2]), "+f"(d[3])
        : "r"(a[0]), "r"(a[1]), "r"(a[2]), "r"(a[3]), "r"(b[0]), "r"(b[1]));
}

// ---------------------------------------------------------------------------
__global__ void zero_kernel() {
    int i = blockIdx.x * 256 + threadIdx.x;
    if (i < BB * KCC * CC) g_S[i] = 0.f;
    if (i < BB * KCC) g_z[i] = 0.f;
}

// ---------------------------------------------------------------------------
// Pass 1 (tf32 mma, 512 threads / 16 warps):
//   Stage B: D[qk,px] = Wqk . x   (warp tile 16qk x 32px)
//   epilogue: elu+1; q -> g_qm; k -> km smem + z partials
//   Stage C: S[kc,c] += km . x^T  (warp tile 32kc x 16c, register-resident)
// ---------------------------------------------------------------------------
__global__ __launch_bounds__(512, 1)
void pass1_kernel(const float* __restrict__ x,
                  const float* __restrict__ Wq, const float* __restrict__ bq,
                  const float* __restrict__ Wk, const float* __restrict__ bk)
{
    const int tid  = threadIdx.x;
    const int b    = blockIdx.y;
    const int blk  = blockIdx.x;
    const int w    = tid >> 5;
    const int lane = tid & 31;
    const int g    = lane >> 2;
    const int t    = lane & 3;

    const uint32_t sb = smem_u32(smf);
    const uint32_t* WsU = (const uint32_t*)(smf + F_WS);
    const uint32_t* xsU = (const uint32_t*)(smf + F_XS);
    const uint32_t* kmU = (const uint32_t*)(smf + F_KM);

    if (tid < 64) smf[F_BIAS + tid] = (tid < KCC) ? bq[tid] : bk[tid - KCC];
    for (int i = tid; i < 64 * 256; i += 512) {
        int qk = i >> 8, c = i & 255;
        smf[F_WS + qk * LDW + c] = (qk < KCC) ? Wq[qk * CC + c] : Wk[(qk - KCC) * CC + c];
    }

    float sc[2][2][4];
#pragma unroll
    for (int mi = 0; mi < 2; mi++)
#pragma unroll
        for (int nj = 0; nj < 2; nj++)
#pragma unroll
            for (int r = 0; r < 4; r++) sc[mi][nj][r] = 0.f;
    float zp[2] = {0.f, 0.f};

    const int qk0   = (w >> 2) * 16;   // 0,16 = q warps; 32,48 = k warps
    const int px0   = (w & 3) * 32;
    const int cbase = w * 16;

    const float* xbase = x + (size_t)b * CC * NN;

    // issue tile-0 chunks (4 chunks of 64 c-rows)
    {
        const float* xb = xbase + (size_t)blk * T1 * TPX;
#pragma unroll
        for (int j = 0; j < 4; j++) {
            for (int u = tid; u < 2048; u += 512) {
                int row = u >> 5, seg = u & 31;
                int c = j * 64 + row;
                cp_async16(sb + (uint32_t)(F_XS + c * LDX + seg * 4) * 4,
                           xb + (size_t)c * NN + seg * 4);
            }
            cp_commit();
        }
    }
    __syncthreads();   // Ws/bias ready

    for (int tt = 0; tt < T1; tt++) {
        const int n0 = (blk * T1 + tt) * TPX;

        // ---- Stage B ----
        float db[4][4];
#pragma unroll
        for (int nj = 0; nj < 4; nj++)
#pragma unroll
            for (int r = 0; r < 4; r++) db[nj][r] = 0.f;

#pragma unroll
        for (int j = 0; j < 4; j++) {
            cp_wait_n(3 - j);
            __syncthreads();
#pragma unroll
            for (int ss = 0; ss < 8; ss++) {
                const int c0 = j * 64 + ss * 8;
                uint32_t a[4];
                const int r0 = qk0 + g;
                a[0] = WsU[r0 * LDW + c0 + t];
                a[1] = WsU[(r0 + 8) * LDW + c0 + t];
                a[2] = WsU[r0 * LDW + c0 + t + 4];
                a[3] = WsU[(r0 + 8) * LDW + c0 + t + 4];
#pragma unroll
                for (int nj = 0; nj < 4; nj++) {
                    uint32_t bb[2];
                    bb[0] = xsU[(c0 + t) * LDX + px0 + 8 * nj + g];
                    bb[1] = xsU[(c0 + t + 4) * LDX + px0 + 8 * nj + g];
                    mma_tf32(db[nj], a, bb);
                }
            }
        }

        // ---- Epilogue ----
        if (w < 8) {
#pragma unroll
            for (int nj = 0; nj < 4; nj++)
#pragma unroll
                for (int r = 0; r < 4; r++) {
                    int qk = qk0 + g + 8 * (r >> 1);
                    int px = px0 + 8 * nj + 2 * t + (r & 1);
                    float v = db[nj][r] + smf[F_BIAS + qk];
                    v = (v > 0.f) ? (v + 1.f) : __expf(v);
                    g_qm[((size_t)b * KCC + qk) * NN + n0 + px] = v;
                }
        } else {
#pragma unroll
            for (int nj = 0; nj < 4; nj++)
#pragma unroll
                for (int r = 0; r < 4; r++) {
                    int kc = qk0 - 32 + g + 8 * (r >> 1);
                    int px = px0 + 8 * nj + 2 * t + (r & 1);
                    float v = db[nj][r] + smf[F_BIAS + 32 + kc];
                    v = (v > 0.f) ? (v + 1.f) : __expf(v);
                    smf[F_KM + kc * LDK + px] = v;
                    zp[r >> 1] += v;
                }
        }
        __syncthreads();   // km visible

        // ---- Stage C ----
#pragma unroll 4
        for (int s = 0; s < 16; s++) {
            const int p0 = s * 8;
            uint32_t a[2][4];
#pragma unroll
            for (int mi = 0; mi < 2; mi++) {
                int r0 = 16 * mi + g;
                a[mi][0] = kmU[r0 * LDK + p0 + t];
                a[mi][1] = kmU[(r0 + 8) * LDK + p0 + t];
                a[mi][2] = kmU[r0 * LDK + p0 + t + 4];
                a[mi][3] = kmU[(r0 + 8) * LDK + p0 + t + 4];
            }
#pragma unroll
            for (int nj = 0; nj < 2; nj++) {
                uint32_t bb[2];
                bb[0] = xsU[(cbase + 8 * nj + g) * LDX + p0 + t];
                bb[1] = xsU[(cbase + 8 * nj + g) * LDX + p0 + t + 4];
                mma_tf32(sc[0][nj], a[0], bb);
                mma_tf32(sc[1][nj], a[1], bb);
            }
        }
        __syncthreads();   // xs/km free

        if (tt + 1 < T1) {
            const float* xb = xbase + (size_t)(blk * T1 + tt + 1) * TPX;
#pragma unroll
            for (int j = 0; j < 4; j++) {
                for (int u = tid; u < 2048; u += 512) {
                    int row = u >> 5, seg = u & 31;
                    int c = j * 64 + row;
                    cp_async16(sb + (uint32_t)(F_XS + c * LDX + seg * 4) * 4,
                               xb + (size_t)c * NN + seg * 4);
                }
                cp_commit();
            }
        }
    }

    // ---- Flush S ----
#pragma unroll
    for (int mi = 0; mi < 2; mi++)
#pragma unroll
        for (int nj = 0; nj < 2; nj++)
#pragma unroll
            for (int r = 0; r < 4; r++) {
                int kc = 16 * mi + g + 8 * (r >> 1);
                int c  = cbase + 8 * nj + 2 * t + (r & 1);
                atomicAdd(&g_S[(b * KCC + kc) * CC + c], sc[mi][nj][r]);
            }
    // ---- Flush z ----
    if (w >= 8) {
#pragma unroll
        for (int rr = 0; rr < 2; rr++) {
            float v = zp[rr];
            v += __shfl_xor_sync(0xffffffffu, v, 1);
            v += __shfl_xor_sync(0xffffffffu, v, 2);
            if (t == 0) atomicAdd(&g_z[b * KCC + qk0 - 32 + g + 8 * rr], v);
        }
    }
}

// ---------------------------------------------------------------------------
// kv = S @ Wv^T + z * bv^T
// ---------------------------------------------------------------------------
__global__ __launch_bounds__(256)
void kv_kernel(const float* __restrict__ Wv, const float* __restrict__ bv)
{
    __shared__ float Ssm[KCC * CC];
    __shared__ float Wsm[32 * CC];
    __shared__ float zsm[KCC];

    const int tid = threadIdx.x;
    const int b   = blockIdx.y;
    const int v0  = blockIdx.x * 32;

    for (int i = tid; i < KCC * CC / 4; i += 256)
        *(float4*)&Ssm[i * 4] = *(const float4*)&g_S[b * KCC * CC + i * 4];
    for (int i = tid; i < 32 * CC / 4; i += 256)
        *(float4*)&Wsm[i * 4] = *(const float4*)&Wv[v0 * CC + i * 4];
    if (tid < KCC) {
        float z = g_z[b * KCC + tid];
        zsm[tid] = z;
        if (blockIdx.x == 0) g_zf[b * KCC + tid] = z;
    }
    __syncthreads();

    const int kc = tid >> 3, j0 = tid & 7;
#pragma unroll
    for (int j = 0; j < 4; j++) {
        int vl = j0 + 8 * j;
        float acc = zsm[kc] * bv[v0 + vl];
        const float* wr = Wsm + vl * CC;
        const float* sr = Ssm + kc * CC;
#pragma unroll 8
        for (int c4 = 0; c4 < 64; c4++) {
            float4 wv = *(const float4*)&wr[c4 * 4];
            float4 s  = *(const float4*)&sr[c4 * 4];
            acc = fmaf(wv.x, s.x, acc);
            acc = fmaf(wv.y, s.y, acc);
            acc = fmaf(wv.z, s.z, acc);
            acc = fmaf(wv.w, s.w, acc);
        }
        g_kv[(b * KCC + kc) * CC + v0 + vl] = acc;
    }
}

// ---------------------------------------------------------------------------
// Pass 2 (tf32 mma): out[c,n] tile 128c x 128n per CTA
//   D = kvT[128c,32k] @ qm[32k,128n]; out = gamma*D/max(qz,eps) + x
// ---------------------------------------------------------------------------
__global__ __launch_bounds__(256)
void pass2_kernel(const float* __restrict__ x,
                  const float* __restrict__ gamma,
                  float* __restrict__ out)
{
    __shared__ float kvT[128 * P2_LDA];   // [c][kc]
    __shared__ float qms[KCC * P2_LDB];   // [kc][n]
    __shared__ float qzs[128];
    __shared__ float zsm[KCC];

    const int tid  = threadIdx.x;
    const int b    = blockIdx.z;
    const int half = blockIdx.y;
    const int n0   = blockIdx.x * 128;
    const int w    = tid >> 5;
    const int lane = tid & 31;
    const int g    = lane >> 2;
    const int t    = lane & 3;

    const uint32_t* kvU = (const uint32_t*)kvT;
    const uint32_t* qmU = (const uint32_t*)qms;

    // kv half -> kvT transposed [c][kc]
    for (int i = tid; i < 32 * 128; i += 256) {
        int kc = i >> 7, c = i & 127;
        kvT[c * P2_LDA + kc] = g_kv[(b * KCC + kc) * CC + half * 128 + c];
    }
    // qm tile [32][128]
    for (int i = tid; i < 32 * 32; i += 256) {
        int k = i >> 5, f = i & 31;
        *(float4*)&qms[k * P2_LDB + f * 4] =
            *(const float4*)&g_qm[((size_t)b * KCC + k) * NN + n0 + f * 4];
    }
    if (tid < KCC) zsm[tid] = g_zf[b * KCC + tid];
    __syncthreads();

    // qz[n]
    if (tid < 128) {
        float s = 0.f;
#pragma unroll
        for (int k = 0; k < KCC; k++) s = fmaf(zsm[k], qms[k * P2_LDB + tid], s);
        qzs[tid] = s;
    }

    // MMA: warp tile 32c x 64n ; c0 = (w>>1)*32, n0w = (w&1)*64
    const int c0  = (w >> 1) * 32;
    const int n0w = (w & 1) * 64;

    float d[2][8][4];
#pragma unroll
    for (int mi = 0; mi < 2; mi++)
#pragma unroll
        for (int nj = 0; nj < 8; nj++)
#pragma unroll
            for (int r = 0; r < 4; r++) d[mi][nj][r] = 0.f;

#pragma unroll
    for (int s = 0; s < 4; s++) {
        const int k0 = s * 8;
        uint32_t a[2][4];
#pragma unroll
        for (int mi = 0; mi < 2; mi++) {
            int r0 = c0 + 16 * mi + g;
            a[mi][0] = kvU[r0 * P2_LDA + k0 + t];
            a[mi][1] = kvU[(r0 + 8) * P2_LDA + k0 + t];
            a[mi][2] = kvU[r0 * P2_LDA + k0 + t + 4];
            a[mi][3] = kvU[(r0 + 8) * P2_LDA + k0 + t + 4];
        }
#pragma unroll
        for (int nj = 0; nj < 8; nj++) {
            uint32_t bb[2];
            bb[0] = qmU[(k0 + t) * P2_LDB + n0w + 8 * nj + g];
            bb[1] = qmU[(k0 + t + 4) * P2_LDB + n0w + 8 * nj + g];
            mma_tf32(d[0][nj], a[0], bb);
            mma_tf32(d[1][nj], a[1], bb);
        }
    }
    __syncthreads();   // qzs ready

    const float gam = gamma[0];
#pragma unroll
    for (int mi = 0; mi < 2; mi++)
#pragma unroll
        for (int nj = 0; nj < 8; nj++)
#pragma unroll
            for (int rr = 0; rr < 2; rr++) {
                int c  = c0 + 16 * mi + g + 8 * rr;
                int nl = n0w + 8 * nj + 2 * t;
                size_t gx = ((size_t)b * CC + half * 128 + c) * NN + n0 + nl;
                float2 xv = *(const float2*)&x[gx];
                float i0 = gam / fmaxf(qzs[nl], 1e-6f);
                float i1 = gam / fmaxf(qzs[nl + 1], 1e-6f);
                float2 o;
                o.x = fmaf(d[mi][nj][2 * rr],     i0, xv.x);
                o.y = fmaf(d[mi][nj][2 * rr + 1], i1, xv.y);
                *(float2*)&out[gx] = o;
            }
}

// ---------------------------------------------------------------------------
extern "C" void kernel_launch(void* const* d_in, const int* in_sizes, int n_in,
                              void* d_out, int out_size)
{
    const float* x     = (const float*)d_in[0];
    const float* Wq    = (const float*)d_in[1];
    const float* bq    = (const float*)d_in[2];
    const float* Wk    = (const float*)d_in[3];
    const float* bk    = (const float*)d_in[4];
    const float* Wv    = (const float*)d_in[5];
    const float* bv    = (const float*)d_in[6];
    const float* gamma = (const float*)d_in[7];
    float* out = (float*)d_out;

    cudaFuncSetAttribute(pass1_kernel, cudaFuncAttributeMaxDynamicSharedMemorySize,
                         SMEM1_BYTES);

    zero_kernel<<<(BB * KCC * CC + 255) / 256, 256>>>();
    pass1_kernel<<<dim3(NB1, BB), 512, SMEM1_BYTES>>>(x, Wq, bq, Wk, bk);
    kv_kernel<<<dim3(8, BB), 256>>>(Wv, bv);
    pass2_kernel<<<dim3(NN / 128, 2, BB), 256>>>(x, gamma, out);
}